// round 5
// baseline (speedup 1.0000x reference)
#include <cuda_runtime.h>
#include <cstdint>

#define B_I 3072   // 256*12 batched signals
#define N_N 2048   // signal length
#define M_M 512    // measurements
#define NITER 100

// ---------------------------------------------------------------------------
// Operand images, plain fp32, fragment order for mma.m16n8k8.tf32, K-chunk 16.
//
// A-image: blocks (bm=row>>7, c=col>>4), 2048 floats each.
//   fi = ((mt*2+ks)*32 + lane)*4 + comp
//   mt=(row>>4)&7, ks=(col>>3)&1, lane=((row&7)<<2)|(col&3),
//   comp=((row>>3)&1) | (((col>>2)&1)<<1)
//   -> float4 at slot = (v(r,c), v(r+8,c), v(r,c+4), v(r+8,c+4)) = one A frag.
// B-image: blocks (bn=n>>7, c=k>>4), 512 float4 each.
//   slot = nt*32 + lane, nt=(n>>3)&15, lane=((n&7)<<2)|(k&3)
//   float4 = (v(n,k0), v(n,k0+4), v(n,k0+8), v(n,k0+12)), k0 = c*16+(lane&3)
//   (comps 0,1 = ks0 b-frag; comps 2,3 = ks1 b-frag)
// ---------------------------------------------------------------------------
__device__ __align__(16) float g_simg[B_I * N_N];   // s   (A-image, NCH=128)
__device__ __align__(16) float g_rimg[B_I * M_M];   // r   (A-image, NCH=32)
__device__ __align__(16) float g_bimg[B_I * M_M];   // b   (A-image, NCH=32)
__device__ __align__(16) float g_B1[M_M * N_N];     // gemm1 B (n=512,  k=2048)
__device__ __align__(16) float g_B2[N_N * M_M];     // gemm2 B (n=2048, k=512)
__device__ __align__(16) float g_B3[N_N * N_N];     // final B (n=2048, k=2048)

// ---------------------------------------------------------------------------
__device__ __forceinline__ uint32_t smem_u32(const void* p) {
    uint32_t a;
    asm("{ .reg .u64 t; cvta.to.shared.u64 t, %1; cvt.u32.u64 %0, t; }"
        : "=r"(a) : "l"(p));
    return a;
}
__device__ __forceinline__ float to_tf32(float x) {
    float r;
    asm("cvt.rna.tf32.f32 %0, %1;" : "=f"(r) : "f"(x));
    return r;
}
__device__ __forceinline__ uint32_t hi_u(float x) {
    return __float_as_uint(to_tf32(x));
}
__device__ __forceinline__ uint32_t lo_u(float x, uint32_t hi) {
    return __float_as_uint(to_tf32(x - __uint_as_float(hi)));
}
__device__ __forceinline__ void cp16(uint32_t saddr, const void* g) {
    asm volatile("cp.async.cg.shared.global [%0], [%1], 16;"
                 :: "r"(saddr), "l"(g) : "memory");
}
#define CP_COMMIT() asm volatile("cp.async.commit_group;" ::: "memory")
#define CP_WAIT2()  asm volatile("cp.async.wait_group 2;" ::: "memory")
#define CP_WAIT1()  asm volatile("cp.async.wait_group 1;" ::: "memory")
#define CP_WAIT0()  asm volatile("cp.async.wait_group 0;" ::: "memory")

__device__ __forceinline__ float4 lds128f(uint32_t a) {
    float4 v;
    asm volatile("ld.shared.v4.f32 {%0,%1,%2,%3}, [%4];"
                 : "=f"(v.x), "=f"(v.y), "=f"(v.z), "=f"(v.w) : "r"(a));
    return v;
}
__device__ __forceinline__ float2 lds64f(uint32_t a) {
    float2 v;
    asm volatile("ld.shared.v2.f32 {%0,%1}, [%2];"
                 : "=f"(v.x), "=f"(v.y) : "r"(a));
    return v;
}
__device__ __forceinline__ void mma8(float* c, uint32_t a0, uint32_t a1,
                                     uint32_t a2, uint32_t a3,
                                     uint32_t b0, uint32_t b1) {
    asm volatile("mma.sync.aligned.m16n8k8.row.col.f32.tf32.tf32.f32 "
                 "{%0,%1,%2,%3}, {%4,%5,%6,%7}, {%8,%9}, {%0,%1,%2,%3};"
                 : "+f"(c[0]), "+f"(c[1]), "+f"(c[2]), "+f"(c[3])
                 : "r"(a0), "r"(a1), "r"(a2), "r"(a3), "r"(b0), "r"(b1));
}

// A-image float index within a (bm, c) block
__device__ __forceinline__ int a_fi(int row, int col) {
    int mt = (row >> 4) & 7, ks = (col >> 3) & 1;
    int ln = ((row & 7) << 2) | (col & 3);
    int cp = ((row >> 3) & 1) | (((col >> 2) & 1) << 1);
    return ((mt * 2 + ks) * 32 + ln) * 4 + cp;
}

// idxs may be int64 or int32
__device__ __forceinline__ int get_idx(const void* idxp, int m) {
    const long long* p64 = (const long long*)idxp;
    if ((p64[0] >> 32) == 0LL) return (int)p64[m];
    return ((const int*)idxp)[m];
}
__device__ __forceinline__ float dct_w(int k) {
    return (k == 0) ? rsqrtf((float)N_N) : sqrtf(2.0f / (float)N_N);
}
// mode 1 (B1): n = measurement row (idx[n]); v = w_k cos(pi(2*idx_n+1)k/4096)
// mode 2 (B2): k = measurement (idx[k]);     v = w_n cos(pi(2*idx_k+1)n/4096)
// mode 3 (B3):                               v = w_k cos(pi(2n+1)k/4096)
__device__ __forceinline__ float bval(int mode, const void* idxs, int n, int k) {
    int t; float w;
    if (mode == 1)      { int j = get_idx(idxs, n); t = ((2*j+1)*k) & 8191; w = dct_w(k); }
    else if (mode == 2) { int j = get_idx(idxs, k); t = ((2*j+1)*n) & 8191; w = dct_w(n); }
    else                { t = ((2*n+1)*k) & 8191;                           w = dct_w(k); }
    return w * cospif((float)t * (1.0f / 4096.0f));
}

// ---------------------------------------------------------------------------
// setup kernels
// ---------------------------------------------------------------------------
__global__ void k_zero_s() {
    int i = blockIdx.x * blockDim.x + threadIdx.x;
    if (i < B_I * N_N / 4) ((float4*)g_simg)[i] = make_float4(0.f, 0.f, 0.f, 0.f);
}

__global__ void k_build_b(const float* __restrict__ x, const void* idxs) {
    int id = blockIdx.x * blockDim.x + threadIdx.x;
    if (id >= B_I * M_M) return;
    int i = id >> 9, m = id & 511;
    float v = x[(size_t)i * N_N + get_idx(idxs, m)] * 100.0f;
    g_bimg[((size_t)(i >> 7) * 32 + (m >> 4)) * 2048 + a_fi(i, m)] = v;
}

// combined builder for B1|B2|B3 (one launch)
#define B1_F4 (4  * 128 * 512)
#define B2_F4 (16 * 32  * 512)
#define B3_F4 (16 * 128 * 512)
__global__ void k_build_Ball(const void* idxs) {
    int id = blockIdx.x * blockDim.x + threadIdx.x;
    float4* img; int mode, NCH, lid;
    if (id < B1_F4)                 { img = (float4*)g_B1; mode = 1; NCH = 128; lid = id; }
    else if (id < B1_F4 + B2_F4)    { img = (float4*)g_B2; mode = 2; NCH = 32;  lid = id - B1_F4; }
    else if (id < B1_F4 + B2_F4 + B3_F4)
                                    { img = (float4*)g_B3; mode = 3; NCH = 128; lid = id - B1_F4 - B2_F4; }
    else return;
    int bn = lid / (NCH * 512);
    int rem = lid - bn * (NCH * 512);
    int c = rem >> 9;
    int rr = rem & 511;
    int nt = rr >> 5, lane = rr & 31;
    int n = bn * 128 + nt * 8 + (lane >> 2);
    int k0 = c * 16 + (lane & 3);
    img[lid] = make_float4(bval(mode, idxs, n, k0),
                           bval(mode, idxs, n, k0 + 4),
                           bval(mode, idxs, n, k0 + 8),
                           bval(mode, idxs, n, k0 + 12));
}

// ---------------------------------------------------------------------------
// tf32-split GEMM: CTA 128x128, 8 warps (2x4), warp tile 64x32.
// K chunks of 16, 3-stage cp.async pipeline (16KB/stage), occ 2.
// MODE 0: rimg = acc - bimg            MODE 1: simg = soft(simg - acc, .05)
// MODE 2: out  = acc * 0.01 (row-major)
// ---------------------------------------------------------------------------
#define SMEM_SZ (3 * 16384)

template<int MODE, int KTOT, int JTOT>
__device__ __forceinline__ void prefetch_chunk(
    uint32_t su, const float4* Ag, const float4* Bg, int c, int tid)
{
    uint32_t d = su + (c % 3) * 16384;
    const float4* a = Ag + (size_t)c * 512;
    const float4* b = Bg + (size_t)c * 512;
    cp16(d + tid * 16,               a + tid);
    cp16(d + (tid + 256) * 16,       a + tid + 256);
    cp16(d + 8192 + tid * 16,        b + tid);
    cp16(d + 8192 + (tid + 256) * 16, b + tid + 256);
}

template<int MODE, int KTOT, int JTOT>
__global__ void __launch_bounds__(256, 2) mma_gemm(
    const float* __restrict__ Aimg, const float* __restrict__ Bimg,
    float* __restrict__ Out, const float* __restrict__ Baux)
{
    constexpr int NC = KTOT / 16;
    extern __shared__ char smem[];
    const uint32_t su = smem_u32(smem);
    const int tid = threadIdx.x, lane = tid & 31, w = tid >> 5;
    const int wm = w >> 2, wn = w & 3;
    const int bx = blockIdx.x, by = blockIdx.y;

    const float4* Ag = (const float4*)Aimg + (size_t)by * NC * 512;
    const float4* Bg = (const float4*)Bimg + (size_t)bx * NC * 512;

    float acc[4][4][4];
    #pragma unroll
    for (int i = 0; i < 4; i++)
        #pragma unroll
        for (int j = 0; j < 4; j++)
            #pragma unroll
            for (int e = 0; e < 4; e++) acc[i][j][e] = 0.0f;

    prefetch_chunk<MODE, KTOT, JTOT>(su, Ag, Bg, 0, tid); CP_COMMIT();
    prefetch_chunk<MODE, KTOT, JTOT>(su, Ag, Bg, 1, tid); CP_COMMIT();
    prefetch_chunk<MODE, KTOT, JTOT>(su, Ag, Bg, 2, tid); CP_COMMIT();

    for (int c = 0; c < NC; c++) {
        if (c + 2 < NC)      { CP_WAIT2(); }
        else if (c + 1 < NC) { CP_WAIT1(); }
        else                 { CP_WAIT0(); }
        __syncthreads();

        const uint32_t sA = su + (c % 3) * 16384;
        const uint32_t sB = sA + 8192;

        #pragma unroll
        for (int ks = 0; ks < 2; ks++) {
            // A fragments (fp32) -> hi
            float4 araw[4];
            uint32_t ahi[4][4];
            #pragma unroll
            for (int mt = 0; mt < 4; mt++) {
                araw[mt] = lds128f(sA + (((wm * 4 + mt) * 2 + ks) * 32 + lane) * 16);
                ahi[mt][0] = hi_u(araw[mt].x); ahi[mt][1] = hi_u(araw[mt].y);
                ahi[mt][2] = hi_u(araw[mt].z); ahi[mt][3] = hi_u(araw[mt].w);
            }
            // B fragments (fp32) -> hi, lo
            uint32_t bhi[4][2], blo[4][2];
            #pragma unroll
            for (int nt = 0; nt < 4; nt++) {
                float2 br = lds64f(sB + ((wn * 4 + nt) * 32 + lane) * 16 + ks * 8);
                bhi[nt][0] = hi_u(br.x);          bhi[nt][1] = hi_u(br.y);
                blo[nt][0] = lo_u(br.x, bhi[nt][0]); blo[nt][1] = lo_u(br.y, bhi[nt][1]);
            }
            // group 1: ahi x bhi
            #pragma unroll
            for (int mt = 0; mt < 4; mt++)
                #pragma unroll
                for (int nt = 0; nt < 4; nt++)
                    mma8(acc[mt][nt], ahi[mt][0], ahi[mt][1], ahi[mt][2], ahi[mt][3],
                         bhi[nt][0], bhi[nt][1]);
            // group 2: ahi x blo
            #pragma unroll
            for (int mt = 0; mt < 4; mt++)
                #pragma unroll
                for (int nt = 0; nt < 4; nt++)
                    mma8(acc[mt][nt], ahi[mt][0], ahi[mt][1], ahi[mt][2], ahi[mt][3],
                         blo[nt][0], blo[nt][1]);
            // alo from araw/ahi, then group 3: alo x bhi
            uint32_t alo[4][4];
            #pragma unroll
            for (int mt = 0; mt < 4; mt++) {
                alo[mt][0] = lo_u(araw[mt].x, ahi[mt][0]);
                alo[mt][1] = lo_u(araw[mt].y, ahi[mt][1]);
                alo[mt][2] = lo_u(araw[mt].z, ahi[mt][2]);
                alo[mt][3] = lo_u(araw[mt].w, ahi[mt][3]);
            }
            #pragma unroll
            for (int mt = 0; mt < 4; mt++)
                #pragma unroll
                for (int nt = 0; nt < 4; nt++)
                    mma8(acc[mt][nt], alo[mt][0], alo[mt][1], alo[mt][2], alo[mt][3],
                         bhi[nt][0], bhi[nt][1]);
        }
        __syncthreads();
        if (c + 3 < NC) {
            prefetch_chunk<MODE, KTOT, JTOT>(su, Ag, Bg, c + 3, tid);
            CP_COMMIT();
        }
    }

    // epilogue
    #pragma unroll
    for (int mt = 0; mt < 4; mt++) {
        #pragma unroll
        for (int nt = 0; nt < 4; nt++) {
            const int row0 = by * 128 + (wm * 4 + mt) * 16 + (lane >> 2);
            const int col0 = bx * 128 + (wn * 4 + nt) * 8 + 2 * (lane & 3);
            float* a = acc[mt][nt];
            #pragma unroll
            for (int e = 0; e < 4; e++) {
                const int row = row0 + (e >> 1) * 8;
                const int col = col0 + (e & 1);
                float v = a[e];
                if (MODE == 2) {
                    Out[(size_t)row * JTOT + col] = v * 0.01f;
                } else {
                    constexpr int NCHO = (MODE == 0) ? (M_M / 16) : (N_N / 16);
                    const size_t base = ((size_t)(row >> 7) * NCHO + (col >> 4)) * 2048;
                    const int fi = a_fi(row, col);
                    if (MODE == 0) {
                        Out[base + fi] = v - Baux[base + fi];
                    } else {
                        float u = Out[base + fi] - v;
                        float t = fabsf(u) - 0.05f;
                        Out[base + fi] = (t > 0.0f) ? copysignf(t, u) : 0.0f;
                    }
                }
            }
        }
    }
}

extern "C" void kernel_launch(void* const* d_in, const int* in_sizes, int n_in,
                              void* d_out, int out_size) {
    const float* x    = (const float*)d_in[0];
    const void*  idxs = d_in[1];
    float*       out  = (float*)d_out;

    float *simg, *rimg, *bimg, *B1, *B2, *B3;
    cudaGetSymbolAddress((void**)&simg, g_simg);
    cudaGetSymbolAddress((void**)&rimg, g_rimg);
    cudaGetSymbolAddress((void**)&bimg, g_bimg);
    cudaGetSymbolAddress((void**)&B1, g_B1);
    cudaGetSymbolAddress((void**)&B2, g_B2);
    cudaGetSymbolAddress((void**)&B3, g_B3);

    cudaFuncSetAttribute(mma_gemm<0, N_N, M_M>,
                         cudaFuncAttributeMaxDynamicSharedMemorySize, SMEM_SZ);
    cudaFuncSetAttribute(mma_gemm<1, M_M, N_N>,
                         cudaFuncAttributeMaxDynamicSharedMemorySize, SMEM_SZ);
    cudaFuncSetAttribute(mma_gemm<2, N_N, N_N>,
                         cudaFuncAttributeMaxDynamicSharedMemorySize, SMEM_SZ);

    k_zero_s   <<<(B_I * N_N / 4 + 255) / 256, 256>>>();
    k_build_b  <<<(B_I * M_M + 255) / 256, 256>>>(x, idxs);
    k_build_Ball<<<(B1_F4 + B2_F4 + B3_F4 + 255) / 256, 256>>>(idxs);

    dim3 g1(M_M / 128, B_I / 128);   // (4, 24)
    dim3 g2(N_N / 128, B_I / 128);   // (16, 24)
    for (int it = 0; it < NITER; ++it) {
        // r = s @ A^T - b
        mma_gemm<0, N_N, M_M><<<g1, 256, SMEM_SZ>>>(simg, B1, rimg, bimg);
        // s = soft(s - r @ A, 0.05)
        mma_gemm<1, M_M, N_N><<<g2, 256, SMEM_SZ>>>(rimg, B2, simg, nullptr);
    }
    // out = idct(s) / SCALE
    mma_gemm<2, N_N, N_N><<<g2, 256, SMEM_SZ>>>(simg, B3, out, nullptr);
}

// round 6
// speedup vs baseline: 1.4007x; 1.4007x over previous
#include <cuda_runtime.h>
#include <cstdint>

#define B_I 3072   // 256*12 batched signals
#define N_N 2048   // signal length
#define M_M 512    // measurements
#define NITER 100

// ---------------------------------------------------------------------------
// All operand images pre-split (tf32 hi/lo) in mma-fragment order, K-chunk 16,
// 64-row/col blocks.
//
// A-image: block (bm=row>>6, c=col>>4) = 2048 floats: [hi 1024][lo 1024].
//   fi = ((mt*2+ks)*32 + lane)*4 + comp
//   mt=(row>>4)&3, ks=(col>>3)&1, lane=((row&7)<<2)|(col&3),
//   comp=((row>>3)&1) | (((col>>2)&1)<<1)
//   -> one LDS128 per plane = one m16k8 A fragment.
// B-image: block (bn=n>>6, c=k>>4) = 512 float4:
//   slot = (nt*2+ks)*32 + lane, nt=(n>>3)&7, lane=((n&7)<<2)|(k&3)
//   float4 = (b0hi, b1hi, b0lo, b1lo), b0=v(n,k0), b1=v(n,k0+4),
//   k0 = c*16 + ks*8 + (lane&3).
// ---------------------------------------------------------------------------
__device__ __align__(16) float g_simg[B_I * N_N * 2];   // s (A-image, NCH=128)
__device__ __align__(16) float g_rimg[B_I * M_M * 2];   // r (A-image, NCH=32)
__device__ __align__(16) float g_bimg[B_I * M_M];       // b (hi-plane layout)
__device__ __align__(16) float g_B1[M_M * N_N * 2];     // gemm1 B (n=512,k=2048)
__device__ __align__(16) float g_B2[N_N * M_M * 2];     // gemm2 B (n=2048,k=512)
__device__ __align__(16) float g_B3[N_N * N_N * 2];     // final B (n=2048,k=2048)

// ---------------------------------------------------------------------------
__device__ __forceinline__ uint32_t smem_u32(const void* p) {
    uint32_t a;
    asm("{ .reg .u64 t; cvta.to.shared.u64 t, %1; cvt.u32.u64 %0, t; }"
        : "=r"(a) : "l"(p));
    return a;
}
__device__ __forceinline__ float to_tf32(float x) {
    float r;
    asm("cvt.rna.tf32.f32 %0, %1;" : "=f"(r) : "f"(x));
    return r;
}
__device__ __forceinline__ void cp16(uint32_t saddr, const void* g) {
    asm volatile("cp.async.cg.shared.global [%0], [%1], 16;"
                 :: "r"(saddr), "l"(g) : "memory");
}
#define CP_COMMIT() asm volatile("cp.async.commit_group;" ::: "memory")
#define CP_WAIT2()  asm volatile("cp.async.wait_group 2;" ::: "memory")
#define CP_WAIT1()  asm volatile("cp.async.wait_group 1;" ::: "memory")
#define CP_WAIT0()  asm volatile("cp.async.wait_group 0;" ::: "memory")

__device__ __forceinline__ uint4 lds128(uint32_t a) {
    uint4 v;
    asm volatile("ld.shared.v4.b32 {%0,%1,%2,%3}, [%4];"
                 : "=r"(v.x), "=r"(v.y), "=r"(v.z), "=r"(v.w) : "r"(a));
    return v;
}
__device__ __forceinline__ void mma8(float* c, const uint4 a,
                                     uint32_t b0, uint32_t b1) {
    asm volatile("mma.sync.aligned.m16n8k8.row.col.f32.tf32.tf32.f32 "
                 "{%0,%1,%2,%3}, {%4,%5,%6,%7}, {%8,%9}, {%0,%1,%2,%3};"
                 : "+f"(c[0]), "+f"(c[1]), "+f"(c[2]), "+f"(c[3])
                 : "r"(a.x), "r"(a.y), "r"(a.z), "r"(a.w), "r"(b0), "r"(b1));
}

// A-image plane index within a (bm, c) block
__device__ __forceinline__ int a_fi(int row, int col) {
    int mt = (row >> 4) & 3, ks = (col >> 3) & 1;
    int ln = ((row & 7) << 2) | (col & 3);
    int cp = ((row >> 3) & 1) | (((col >> 2) & 1) << 1);
    return ((mt * 2 + ks) * 32 + ln) * 4 + cp;
}

// idxs may be int64 or int32
__device__ __forceinline__ int get_idx(const void* idxp, int m) {
    const long long* p64 = (const long long*)idxp;
    if ((p64[0] >> 32) == 0LL) return (int)p64[m];
    return ((const int*)idxp)[m];
}
__device__ __forceinline__ float dct_w(int k) {
    return (k == 0) ? rsqrtf((float)N_N) : sqrtf(2.0f / (float)N_N);
}
// mode 1 (B1): n = measurement (idx[n]); v = w_k cos(pi(2*idx_n+1)k/4096)
// mode 2 (B2): k = measurement (idx[k]); v = w_n cos(pi(2*idx_k+1)n/4096)
// mode 3 (B3):                           v = w_k cos(pi(2n+1)k/4096)
__device__ __forceinline__ float bval(int mode, const void* idxs, int n, int k) {
    int t; float w;
    if (mode == 1)      { int j = get_idx(idxs, n); t = ((2*j+1)*k) & 8191; w = dct_w(k); }
    else if (mode == 2) { int j = get_idx(idxs, k); t = ((2*j+1)*n) & 8191; w = dct_w(n); }
    else                { t = ((2*n+1)*k) & 8191;                           w = dct_w(k); }
    return w * cospif((float)t * (1.0f / 4096.0f));
}

// ---------------------------------------------------------------------------
// setup kernels
// ---------------------------------------------------------------------------
__global__ void k_zero_s() {
    int i = blockIdx.x * blockDim.x + threadIdx.x;
    if (i < B_I * N_N * 2 / 4)
        ((float4*)g_simg)[i] = make_float4(0.f, 0.f, 0.f, 0.f);
}

__global__ void k_build_b(const float* __restrict__ x, const void* idxs) {
    int id = blockIdx.x * blockDim.x + threadIdx.x;
    if (id >= B_I * M_M) return;
    int i = id >> 9, m = id & 511;
    float v = x[(size_t)i * N_N + get_idx(idxs, m)] * 100.0f;
    g_bimg[((size_t)(i >> 6) * 32 + (m >> 4)) * 1024 + a_fi(i, m)] = v;
}

// combined builder for B1|B2|B3 (one launch).  Per (bn, c) block = 512 float4.
#define B1_F4 (8  * 128 * 512)
#define B2_F4 (32 * 32  * 512)
#define B3_F4 (32 * 128 * 512)
__global__ void k_build_Ball(const void* idxs) {
    int id = blockIdx.x * blockDim.x + threadIdx.x;
    float4* img; int mode, NCH, lid;
    if (id < B1_F4)              { img = (float4*)g_B1; mode = 1; NCH = 128; lid = id; }
    else if (id < B1_F4 + B2_F4) { img = (float4*)g_B2; mode = 2; NCH = 32;  lid = id - B1_F4; }
    else if (id < B1_F4 + B2_F4 + B3_F4)
                                 { img = (float4*)g_B3; mode = 3; NCH = 128; lid = id - B1_F4 - B2_F4; }
    else return;
    int bn  = lid / (NCH * 512);
    int rem = lid - bn * (NCH * 512);
    int c    = rem >> 9;
    int slot = rem & 511;
    int nt = slot >> 6, ks = (slot >> 5) & 1, lane = slot & 31;
    int n  = bn * 64 + nt * 8 + (lane >> 2);
    int k0 = c * 16 + ks * 8 + (lane & 3);
    float v0 = bval(mode, idxs, n, k0);
    float v1 = bval(mode, idxs, n, k0 + 4);
    float h0 = to_tf32(v0), h1 = to_tf32(v1);
    img[lid] = make_float4(h0, h1, to_tf32(v0 - h0), to_tf32(v1 - h1));
}

// ---------------------------------------------------------------------------
// tf32-split GEMM: CTA 64x64, 4 warps (2x2), warp tile 32x32 (2 m-tiles x
// 4 n-tiles).  K chunks of 16, 3-stage cp.async (16KB/stage = A 8K + B 8K).
// MODE 0: rimg = acc - bimg          MODE 1: simg = soft(simg - acc, .05)
// MODE 2: out  = acc * 0.01 (row-major)
// ---------------------------------------------------------------------------
#define SMEM_SZ (3 * 16384)

__device__ __forceinline__ void prefetch_chunk(
    uint32_t su, const float4* Ag, const float4* Bg, int c, int tid)
{
    uint32_t d = su + (c % 3) * 16384;
    const float4* a = Ag + (size_t)c * 512;
    const float4* b = Bg + (size_t)c * 512;
    #pragma unroll
    for (int u = 0; u < 4; u++) {
        cp16(d + (tid + u * 128) * 16,        a + tid + u * 128);
        cp16(d + 8192 + (tid + u * 128) * 16, b + tid + u * 128);
    }
}

template<int MODE, int KTOT, int JTOT>
__global__ void __launch_bounds__(128, 4) mma_gemm(
    const float* __restrict__ Aimg, const float* __restrict__ Bimg,
    float* __restrict__ Out, const float* __restrict__ Baux)
{
    constexpr int NC = KTOT / 16;
    extern __shared__ char smem[];
    const uint32_t su = smem_u32(smem);
    const int tid = threadIdx.x, lane = tid & 31, w = tid >> 5;
    const int wm = w >> 1, wn = w & 1;
    const int bx = blockIdx.x, by = blockIdx.y;

    const float4* Ag = (const float4*)Aimg + (size_t)by * NC * 512;
    const float4* Bg = (const float4*)Bimg + (size_t)bx * NC * 512;

    float acc[2][4][4];
    #pragma unroll
    for (int i = 0; i < 2; i++)
        #pragma unroll
        for (int j = 0; j < 4; j++)
            #pragma unroll
            for (int e = 0; e < 4; e++) acc[i][j][e] = 0.0f;

    prefetch_chunk(su, Ag, Bg, 0, tid); CP_COMMIT();
    prefetch_chunk(su, Ag, Bg, 1, tid); CP_COMMIT();
    prefetch_chunk(su, Ag, Bg, 2, tid); CP_COMMIT();

    for (int c = 0; c < NC; c++) {
        if (c + 2 < NC)      { CP_WAIT2(); }
        else if (c + 1 < NC) { CP_WAIT1(); }
        else                 { CP_WAIT0(); }
        __syncthreads();

        const uint32_t sA = su + (c % 3) * 16384;
        const uint32_t sB = sA + 8192;

        #pragma unroll
        for (int ks = 0; ks < 2; ks++) {
            uint4 ahi[2], alo[2], bb[4];
            #pragma unroll
            for (int mt = 0; mt < 2; mt++) {
                uint32_t ad = sA + (((wm * 2 + mt) * 2 + ks) * 32 + lane) * 16;
                ahi[mt] = lds128(ad);
                alo[mt] = lds128(ad + 4096);
            }
            #pragma unroll
            for (int nt = 0; nt < 4; nt++)
                bb[nt] = lds128(sB + (((wn * 4 + nt) * 2 + ks) * 32 + lane) * 16);
            #pragma unroll
            for (int mt = 0; mt < 2; mt++)
                #pragma unroll
                for (int nt = 0; nt < 4; nt++)
                    mma8(acc[mt][nt], ahi[mt], bb[nt].x, bb[nt].y);   // hi*hi
            #pragma unroll
            for (int mt = 0; mt < 2; mt++)
                #pragma unroll
                for (int nt = 0; nt < 4; nt++)
                    mma8(acc[mt][nt], ahi[mt], bb[nt].z, bb[nt].w);   // hi*lo
            #pragma unroll
            for (int mt = 0; mt < 2; mt++)
                #pragma unroll
                for (int nt = 0; nt < 4; nt++)
                    mma8(acc[mt][nt], alo[mt], bb[nt].x, bb[nt].y);   // lo*hi
        }
        __syncthreads();
        if (c + 3 < NC) {
            prefetch_chunk(su, Ag, Bg, c + 3, tid);
            CP_COMMIT();
        }
    }

    // epilogue
    #pragma unroll
    for (int mt = 0; mt < 2; mt++) {
        #pragma unroll
        for (int nt = 0; nt < 4; nt++) {
            const int row0 = by * 64 + (wm * 2 + mt) * 16 + (lane >> 2);
            const int col0 = bx * 64 + (wn * 4 + nt) * 8 + 2 * (lane & 3);
            float* a = acc[mt][nt];
            #pragma unroll
            for (int e = 0; e < 4; e++) {
                const int row = row0 + (e >> 1) * 8;
                const int col = col0 + (e & 1);
                float v = a[e];
                if (MODE == 2) {
                    Out[(size_t)row * JTOT + col] = v * 0.01f;
                } else {
                    constexpr int NCHO = (MODE == 0) ? (M_M / 16) : (N_N / 16);
                    const size_t blk = (size_t)(row >> 6) * NCHO + (col >> 4);
                    const int fi = a_fi(row, col);
                    const size_t base = blk * 2048;
                    if (MODE == 0) {
                        v -= Baux[blk * 1024 + fi];
                    } else {
                        float so = Out[base + fi] + Out[base + 1024 + fi];
                        float u = so - v;
                        float t = fabsf(u) - 0.05f;
                        v = (t > 0.0f) ? copysignf(t, u) : 0.0f;
                    }
                    float hi = to_tf32(v);
                    Out[base + fi]        = hi;
                    Out[base + 1024 + fi] = to_tf32(v - hi);
                }
            }
        }
    }
}

extern "C" void kernel_launch(void* const* d_in, const int* in_sizes, int n_in,
                              void* d_out, int out_size) {
    const float* x    = (const float*)d_in[0];
    const void*  idxs = d_in[1];
    float*       out  = (float*)d_out;

    float *simg, *rimg, *bimg, *B1, *B2, *B3;
    cudaGetSymbolAddress((void**)&simg, g_simg);
    cudaGetSymbolAddress((void**)&rimg, g_rimg);
    cudaGetSymbolAddress((void**)&bimg, g_bimg);
    cudaGetSymbolAddress((void**)&B1, g_B1);
    cudaGetSymbolAddress((void**)&B2, g_B2);
    cudaGetSymbolAddress((void**)&B3, g_B3);

    cudaFuncSetAttribute(mma_gemm<0, N_N, M_M>,
                         cudaFuncAttributeMaxDynamicSharedMemorySize, SMEM_SZ);
    cudaFuncSetAttribute(mma_gemm<1, M_M, N_N>,
                         cudaFuncAttributeMaxDynamicSharedMemorySize, SMEM_SZ);
    cudaFuncSetAttribute(mma_gemm<2, N_N, N_N>,
                         cudaFuncAttributeMaxDynamicSharedMemorySize, SMEM_SZ);

    k_zero_s   <<<(B_I * N_N * 2 / 4 + 255) / 256, 256>>>();
    k_build_b  <<<(B_I * M_M + 255) / 256, 256>>>(x, idxs);
    k_build_Ball<<<(B1_F4 + B2_F4 + B3_F4 + 255) / 256, 256>>>(idxs);

    dim3 g1(M_M / 64, B_I / 64);   // (8, 48)  = 384 CTAs
    dim3 g2(N_N / 64, B_I / 64);   // (32, 48) = 1536 CTAs
    for (int it = 0; it < NITER; ++it) {
        // r = s @ A^T - b
        mma_gemm<0, N_N, M_M><<<g1, 128, SMEM_SZ>>>(simg, B1, rimg, bimg);
        // s = soft(s - r @ A, 0.05)
        mma_gemm<1, M_M, N_N><<<g2, 128, SMEM_SZ>>>(rimg, B2, simg, nullptr);
    }
    // out = idct(s) / SCALE
    mma_gemm<2, N_N, N_N><<<g2, 128, SMEM_SZ>>>(simg, B3, out, nullptr);
}

// round 7
// speedup vs baseline: 2.5926x; 1.8510x over previous
#include <cuda_runtime.h>
#include <cuda_bf16.h>
#include <cstdint>

#define B_I 3072   // 256*12 batched signals
#define N_N 2048   // signal length
#define M_M 512    // measurements
#define NITER 100

typedef unsigned int u32;

// ---------------------------------------------------------------------------
// bf16x3 split GEMM operands, fragment order for mma.m16n8k16.bf16.
// K-chunk 32, blocks of 64 rows/cols.
//
// A-image block (bm=row>>6, c=col>>5): 2048 u32 = [hi plane 1024][lo plane 1024]
//   u32 index: ui = ((mt*2+ks)*32 + lane)*4 + comp
//   mt=(row>>4)&3, ks=(col>>4)&1, lane=((row&7)<<2)|((col>>1)&3),
//   comp=((row>>3)&1) | (((col>>3)&1)<<1);  u32 = bf16x2 of cols (kp, kp+1)
//   -> one LDS128 per plane = one m16k16 A fragment (4 regs).
// B-image block (bn=n>>6, c=k>>5): 512 uint4 slots:
//   slot = (nt*2+ks)*32 + lane, nt=(n>>3)&7, lane=((n&7)<<2)|((k>>1)&3)
//   uint4 = (b0hi, b1hi, b0lo, b1lo); b0 = bf16x2 (k0,k0+1), b1 = (k0+8,k0+9),
//   k0 = c*32 + ks*16 + 2*(lane&3).
// s additionally kept as exact fp32 plane: per block 2048 floats, idx ui*2+(col&1).
// ---------------------------------------------------------------------------
__device__ __align__(16) u32   g_s_bf [B_I * N_N];   // s bf16 planes (NCH=64)
__device__ __align__(16) float g_s_f32[B_I * N_N];   // s exact fp32 (same blocks)
__device__ __align__(16) u32   g_r_bf [B_I * M_M];   // r bf16 planes (NCH=16)
__device__ __align__(16) float g_bimg [B_I * M_M];   // b fp32 (r-image indexing)
__device__ __align__(16) u32   g_B1[M_M * N_N];      // gemm1 B (n=512,  k=2048)
__device__ __align__(16) u32   g_B2[N_N * M_M];      // gemm2 B (n=2048, k=512)
__device__ __align__(16) u32   g_B3[N_N * N_N];      // final B (n=2048, k=2048)

// ---------------------------------------------------------------------------
__device__ __forceinline__ uint32_t smem_u32(const void* p) {
    uint32_t a;
    asm("{ .reg .u64 t; cvta.to.shared.u64 t, %1; cvt.u32.u64 %0, t; }"
        : "=r"(a) : "l"(p));
    return a;
}
__device__ __forceinline__ float bfhi(float v) {
    return __bfloat162float(__float2bfloat16_rn(v));
}
__device__ __forceinline__ u32 packbf(float a, float b) {
    __nv_bfloat162 t = __floats2bfloat162_rn(a, b);   // x=a (low), y=b (high)
    return *reinterpret_cast<u32*>(&t);
}
__device__ __forceinline__ void cp16(uint32_t saddr, const void* g) {
    asm volatile("cp.async.cg.shared.global [%0], [%1], 16;"
                 :: "r"(saddr), "l"(g) : "memory");
}
#define CP_COMMIT() asm volatile("cp.async.commit_group;" ::: "memory")
#define CP_WAIT2()  asm volatile("cp.async.wait_group 2;" ::: "memory")
#define CP_WAIT1()  asm volatile("cp.async.wait_group 1;" ::: "memory")
#define CP_WAIT0()  asm volatile("cp.async.wait_group 0;" ::: "memory")

__device__ __forceinline__ uint4 lds128(uint32_t a) {
    uint4 v;
    asm volatile("ld.shared.v4.b32 {%0,%1,%2,%3}, [%4];"
                 : "=r"(v.x), "=r"(v.y), "=r"(v.z), "=r"(v.w) : "r"(a));
    return v;
}
__device__ __forceinline__ void mma16(float* c, const uint4 a,
                                      u32 b0, u32 b1) {
    asm volatile("mma.sync.aligned.m16n8k16.row.col.f32.bf16.bf16.f32 "
                 "{%0,%1,%2,%3}, {%4,%5,%6,%7}, {%8,%9}, {%0,%1,%2,%3};"
                 : "+f"(c[0]), "+f"(c[1]), "+f"(c[2]), "+f"(c[3])
                 : "r"(a.x), "r"(a.y), "r"(a.z), "r"(a.w), "r"(b0), "r"(b1));
}

// A-image u32 index within a (bm, c) block plane; col = column within chunk (0..31)
__device__ __forceinline__ int a_ui(int row, int col) {
    int mt = (row >> 4) & 3, ks = (col >> 4) & 1;
    int ln = ((row & 7) << 2) | ((col >> 1) & 3);
    int cp = ((row >> 3) & 1) | (((col >> 3) & 1) << 1);
    return ((mt * 2 + ks) * 32 + ln) * 4 + cp;
}

// idxs may be int64 or int32
__device__ __forceinline__ int get_idx(const void* idxp, int m) {
    const long long* p64 = (const long long*)idxp;
    if ((p64[0] >> 32) == 0LL) return (int)p64[m];
    return ((const int*)idxp)[m];
}
__device__ __forceinline__ float dct_w(int k) {
    return (k == 0) ? rsqrtf((float)N_N) : sqrtf(2.0f / (float)N_N);
}
// mode 1 (B1): n = measurement (idx[n]); v = w_k cos(pi(2*idx_n+1)k/4096)
// mode 2 (B2): k = measurement (idx[k]); v = w_n cos(pi(2*idx_k+1)n/4096)
// mode 3 (B3):                           v = w_k cos(pi(2n+1)k/4096)
__device__ __forceinline__ float bval(int mode, const void* idxs, int n, int k) {
    int t; float w;
    if (mode == 1)      { int j = get_idx(idxs, n); t = ((2*j+1)*k) & 8191; w = dct_w(k); }
    else if (mode == 2) { int j = get_idx(idxs, k); t = ((2*j+1)*n) & 8191; w = dct_w(n); }
    else                { t = ((2*n+1)*k) & 8191;                           w = dct_w(k); }
    return w * cospif((float)t * (1.0f / 4096.0f));
}

// ---------------------------------------------------------------------------
// setup
// ---------------------------------------------------------------------------
__global__ void k_zero_s() {
    int i = blockIdx.x * blockDim.x + threadIdx.x;
    if (i < B_I * N_N / 4) {
        ((uint4*)g_s_bf)[i] = make_uint4(0, 0, 0, 0);
        ((float4*)g_s_f32)[i] = make_float4(0.f, 0.f, 0.f, 0.f);
    }
}

__global__ void k_build_b(const float* __restrict__ x, const void* idxs) {
    int id = blockIdx.x * blockDim.x + threadIdx.x;
    if (id >= B_I * M_M) return;
    int i = id >> 9, m = id & 511;
    float v = x[(size_t)i * N_N + get_idx(idxs, m)] * 100.0f;
    size_t blk = (size_t)(i >> 6) * 16 + (m >> 5);
    g_bimg[blk * 2048 + a_ui(i, m & 31) * 2 + (m & 1)] = v;
}

// combined builder: per uint4 slot computes 4 bf16x2 words
#define B1_SL (8  * 64 * 512)
#define B2_SL (32 * 16 * 512)
#define B3_SL (32 * 64 * 512)
__global__ void k_build_Ball(const void* idxs) {
    int id = blockIdx.x * blockDim.x + threadIdx.x;
    uint4* img; int mode, NCH, lid;
    if (id < B1_SL)              { img = (uint4*)g_B1; mode = 1; NCH = 64; lid = id; }
    else if (id < B1_SL + B2_SL) { img = (uint4*)g_B2; mode = 2; NCH = 16; lid = id - B1_SL; }
    else if (id < B1_SL + B2_SL + B3_SL)
                                 { img = (uint4*)g_B3; mode = 3; NCH = 64; lid = id - B1_SL - B2_SL; }
    else return;
    int bn  = lid / (NCH * 512);
    int rem = lid - bn * (NCH * 512);
    int c    = rem >> 9;
    int slot = rem & 511;
    int nt = slot >> 6, ks = (slot >> 5) & 1, lane = slot & 31;
    int n  = bn * 64 + nt * 8 + (lane >> 2);
    int k0 = c * 32 + ks * 16 + 2 * (lane & 3);
    float v0 = bval(mode, idxs, n, k0);
    float v1 = bval(mode, idxs, n, k0 + 1);
    float v8 = bval(mode, idxs, n, k0 + 8);
    float v9 = bval(mode, idxs, n, k0 + 9);
    float h0 = bfhi(v0), h1 = bfhi(v1), h8 = bfhi(v8), h9 = bfhi(v9);
    img[lid] = make_uint4(packbf(h0, h1), packbf(h8, h9),
                          packbf(v0 - h0, v1 - h1), packbf(v8 - h8, v9 - h9));
}

// ---------------------------------------------------------------------------
// bf16x3 GEMM: CTA 64x64, 4 warps (2x2), warp tile 32x32.  K-chunk 32,
// 3-stage cp.async (16KB/stage = A 8K + B 8K), occ 4.
// MODE 0: r = acc - b      MODE 1: s = soft(s_f32 - acc, .05)   MODE 2: out = acc*.01
// ---------------------------------------------------------------------------
#define SMEM_SZ (3 * 16384)

__device__ __forceinline__ void prefetch_chunk(
    uint32_t su, const uint4* Ag, const uint4* Bg, int c, int tid)
{
    uint32_t d = su + (c % 3) * 16384;
    const uint4* a = Ag + (size_t)c * 512;
    const uint4* b = Bg + (size_t)c * 512;
    #pragma unroll
    for (int u = 0; u < 4; u++) {
        cp16(d + (tid + u * 128) * 16,        a + tid + u * 128);
        cp16(d + 8192 + (tid + u * 128) * 16, b + tid + u * 128);
    }
}

template<int MODE, int KTOT, int JTOT>
__global__ void __launch_bounds__(128, 4) mma_gemm(
    const u32* __restrict__ Aimg, const u32* __restrict__ Bimg,
    u32* __restrict__ OutBf, float* __restrict__ OutF,
    const float* __restrict__ Baux)
{
    constexpr int NC = KTOT / 32;
    extern __shared__ char smem[];
    const uint32_t su = smem_u32(smem);
    const int tid = threadIdx.x, lane = tid & 31, w = tid >> 5;
    const int wm = w >> 1, wn = w & 1;
    const int bx = blockIdx.x, by = blockIdx.y;

    const uint4* Ag = (const uint4*)Aimg + (size_t)by * NC * 512;
    const uint4* Bg = (const uint4*)Bimg + (size_t)bx * NC * 512;

    float acc[2][4][4];
    #pragma unroll
    for (int i = 0; i < 2; i++)
        #pragma unroll
        for (int j = 0; j < 4; j++)
            #pragma unroll
            for (int e = 0; e < 4; e++) acc[i][j][e] = 0.0f;

    prefetch_chunk(su, Ag, Bg, 0, tid); CP_COMMIT();
    prefetch_chunk(su, Ag, Bg, 1, tid); CP_COMMIT();
    prefetch_chunk(su, Ag, Bg, 2, tid); CP_COMMIT();

    for (int c = 0; c < NC; c++) {
        if (c + 2 < NC)      { CP_WAIT2(); }
        else if (c + 1 < NC) { CP_WAIT1(); }
        else                 { CP_WAIT0(); }
        __syncthreads();

        const uint32_t sA = su + (c % 3) * 16384;
        const uint32_t sB = sA + 8192;

        #pragma unroll
        for (int ks = 0; ks < 2; ks++) {
            uint4 ahi[2], alo[2], bb[4];
            #pragma unroll
            for (int mt = 0; mt < 2; mt++) {
                uint32_t ad = sA + (((wm * 2 + mt) * 2 + ks) * 32 + lane) * 16;
                ahi[mt] = lds128(ad);
                alo[mt] = lds128(ad + 4096);
            }
            #pragma unroll
            for (int nt = 0; nt < 4; nt++)
                bb[nt] = lds128(sB + (((wn * 4 + nt) * 2 + ks) * 32 + lane) * 16);
            #pragma unroll
            for (int mt = 0; mt < 2; mt++)
                #pragma unroll
                for (int nt = 0; nt < 4; nt++)
                    mma16(acc[mt][nt], ahi[mt], bb[nt].x, bb[nt].y);  // hi*hi
            #pragma unroll
            for (int mt = 0; mt < 2; mt++)
                #pragma unroll
                for (int nt = 0; nt < 4; nt++)
                    mma16(acc[mt][nt], ahi[mt], bb[nt].z, bb[nt].w);  // hi*lo
            #pragma unroll
            for (int mt = 0; mt < 2; mt++)
                #pragma unroll
                for (int nt = 0; nt < 4; nt++)
                    mma16(acc[mt][nt], alo[mt], bb[nt].x, bb[nt].y);  // lo*hi
        }
        __syncthreads();
        if (c + 3 < NC) {
            prefetch_chunk(su, Ag, Bg, c + 3, tid);
            CP_COMMIT();
        }
    }

    // epilogue: per tile, two row-halves, each covering cols (col, col+1)
    #pragma unroll
    for (int mt = 0; mt < 2; mt++) {
        #pragma unroll
        for (int nt = 0; nt < 4; nt++) {
            const int row0 = by * 64 + (wm * 2 + mt) * 16 + (lane >> 2);
            const int col  = bx * 64 + (wn * 4 + nt) * 8 + 2 * (lane & 3);
            float* a = acc[mt][nt];
            #pragma unroll
            for (int h = 0; h < 2; h++) {
                const int row = row0 + h * 8;
                float v0 = a[2 * h], v1 = a[2 * h + 1];
                if (MODE == 2) {
                    *(float2*)&OutF[(size_t)row * JTOT + col] =
                        make_float2(v0 * 0.01f, v1 * 0.01f);
                } else {
                    constexpr int NCHO = (MODE == 0) ? (M_M / 32) : (N_N / 32);
                    const size_t blk = (size_t)(row >> 6) * NCHO + (col >> 5);
                    const int ui = a_ui(row, col & 31);
                    if (MODE == 0) {
                        float2 bv = *(const float2*)&Baux[blk * 2048 + ui * 2];
                        v0 -= bv.x; v1 -= bv.y;
                    } else {
                        float2 so = *(const float2*)&OutF[blk * 2048 + ui * 2];
                        float u0 = so.x - v0, u1 = so.y - v1;
                        float t0 = fabsf(u0) - 0.05f, t1 = fabsf(u1) - 0.05f;
                        v0 = (t0 > 0.0f) ? copysignf(t0, u0) : 0.0f;
                        v1 = (t1 > 0.0f) ? copysignf(t1, u1) : 0.0f;
                        *(float2*)&OutF[blk * 2048 + ui * 2] = make_float2(v0, v1);
                    }
                    float h0 = bfhi(v0), h1 = bfhi(v1);
                    OutBf[blk * 2048 + ui]        = packbf(h0, h1);
                    OutBf[blk * 2048 + 1024 + ui] = packbf(v0 - h0, v1 - h1);
                }
            }
        }
    }
}

extern "C" void kernel_launch(void* const* d_in, const int* in_sizes, int n_in,
                              void* d_out, int out_size) {
    const float* x    = (const float*)d_in[0];
    const void*  idxs = d_in[1];
    float*       out  = (float*)d_out;

    u32 *sbf, *rbf, *B1, *B2, *B3;
    float *sf32, *bimg;
    cudaGetSymbolAddress((void**)&sbf,  g_s_bf);
    cudaGetSymbolAddress((void**)&sf32, g_s_f32);
    cudaGetSymbolAddress((void**)&rbf,  g_r_bf);
    cudaGetSymbolAddress((void**)&bimg, g_bimg);
    cudaGetSymbolAddress((void**)&B1, g_B1);
    cudaGetSymbolAddress((void**)&B2, g_B2);
    cudaGetSymbolAddress((void**)&B3, g_B3);

    cudaFuncSetAttribute(mma_gemm<0, N_N, M_M>,
                         cudaFuncAttributeMaxDynamicSharedMemorySize, SMEM_SZ);
    cudaFuncSetAttribute(mma_gemm<1, M_M, N_N>,
                         cudaFuncAttributeMaxDynamicSharedMemorySize, SMEM_SZ);
    cudaFuncSetAttribute(mma_gemm<2, N_N, N_N>,
                         cudaFuncAttributeMaxDynamicSharedMemorySize, SMEM_SZ);

    k_zero_s   <<<(B_I * N_N / 4 + 255) / 256, 256>>>();
    k_build_b  <<<(B_I * M_M + 255) / 256, 256>>>(x, idxs);
    k_build_Ball<<<(B1_SL + B2_SL + B3_SL + 255) / 256, 256>>>(idxs);

    dim3 g1(M_M / 64, B_I / 64);   // (8, 48)  = 384 CTAs
    dim3 g2(N_N / 64, B_I / 64);   // (32, 48) = 1536 CTAs
    for (int it = 0; it < NITER; ++it) {
        // r = s @ A^T - b
        mma_gemm<0, N_N, M_M><<<g1, 128, SMEM_SZ>>>(sbf, B1, rbf, nullptr, bimg);
        // s = soft(s - r @ A, 0.05)
        mma_gemm<1, M_M, N_N><<<g2, 128, SMEM_SZ>>>(rbf, B2, sbf, sf32, nullptr);
    }
    // out = idct(s) / SCALE
    mma_gemm<2, N_N, N_N><<<g2, 128, SMEM_SZ>>>(sbf, B3, nullptr, out, nullptr);
}